// round 2
// baseline (speedup 1.0000x reference)
#include <cuda_runtime.h>
#include <math.h>

#define HH 240
#define WW 320
#define HWP (HH*WW)
#define BB 4
#define CIN 64
#define COUT 24
#define HS 120
#define WS 160
#define NUMK 8

// ---- scratch (static device globals: allowed; no allocation) ----
__device__ float g_oa[BB*COUT*HWP];      // conv output: [b][ch][y][x] (ch 0..15 offsets, 16..23 aff_raw)
__device__ float g_fea[BB*8*HWP];        // upsampled features CHW
__device__ float g_feahwc[BB*HWP*8];     // upsampled features HWC

// ============================================================================
// bilinear with zeros padding (matches reference _bilinear_zeros)
// ============================================================================
__device__ __forceinline__ float bilin0(const float* __restrict__ img, float x, float y,
                                        int Hi, int Wi) {
    float xf = floorf(x), yf = floorf(y);
    float wx = x - xf, wy = y - yf;
    int x0 = (int)xf, y0 = (int)yf;
    int x1 = x0 + 1, y1 = y0 + 1;

    bool xv0 = (x0 >= 0) && (x0 <= Wi - 1);
    bool xv1 = (x1 >= 0) && (x1 <= Wi - 1);
    bool yv0 = (y0 >= 0) && (y0 <= Hi - 1);
    bool yv1 = (y1 >= 0) && (y1 <= Hi - 1);

    int xc0 = min(max(x0, 0), Wi - 1);
    int xc1 = min(max(x1, 0), Wi - 1);
    int yc0 = min(max(y0, 0), Hi - 1);
    int yc1 = min(max(y1, 0), Hi - 1);

    float v00 = (xv0 && yv0) ? img[yc0 * Wi + xc0] : 0.0f;
    float v10 = (xv1 && yv0) ? img[yc0 * Wi + xc1] : 0.0f;
    float v01 = (xv0 && yv1) ? img[yc1 * Wi + xc0] : 0.0f;
    float v11 = (xv1 && yv1) ? img[yc1 * Wi + xc1] : 0.0f;

    return v00 * ((1.0f - wy) * (1.0f - wx))
         + v10 * ((1.0f - wy) * wx)
         + v01 * (wy * (1.0f - wx))
         + v11 * (wy * wx);
}

// ============================================================================
// Kernel 1: 2x bilinear upsample of tgtimg_fea (jax.image.resize 'bilinear':
// half-pixel centers; edge taps collapse to weight 1.0 on the nearest sample,
// which equals index-clamping with weights 0.25/0.75)
// ============================================================================
__global__ void upsample_kernel(const float* __restrict__ tgt) {
    int idx = blockIdx.x * blockDim.x + threadIdx.x;
    if (idx >= BB * HWP) return;
    int b = idx / HWP;
    int P = idx - b * HWP;
    int y = P / WW, x = P - (P / WW) * WW;

    int ty = y >> 1, tx = x >> 1;
    int y0, y1, x0, x1;
    float wy0, wy1, wx0, wx1;
    if (y & 1) { y0 = ty; y1 = min(ty + 1, HS - 1); wy0 = 0.75f; wy1 = 0.25f; }
    else       { y0 = max(ty - 1, 0); y1 = ty;      wy0 = 0.25f; wy1 = 0.75f; }
    if (x & 1) { x0 = tx; x1 = min(tx + 1, WS - 1); wx0 = 0.75f; wx1 = 0.25f; }
    else       { x0 = max(tx - 1, 0); x1 = tx;      wx0 = 0.25f; wx1 = 0.75f; }

    const float* base = tgt + b * 8 * HS * WS;
    #pragma unroll
    for (int c = 0; c < 8; c++) {
        const float* pl = base + c * HS * WS;
        float r0 = wx0 * pl[y0 * WS + x0] + wx1 * pl[y0 * WS + x1];
        float r1 = wx0 * pl[y1 * WS + x0] + wx1 * pl[y1 * WS + x1];
        float v = wy0 * r0 + wy1 * r1;
        g_fea[(b * 8 + c) * HWP + P] = v;
        g_feahwc[(b * HWP + P) * 8 + c] = v;
    }
}

// ============================================================================
// Kernel 2: zero the reference-offset channels (8,9) of offset_full
// ============================================================================
__global__ void zero_kernel(float* __restrict__ out) {
    int idx = blockIdx.x * blockDim.x + threadIdx.x;
    if (idx >= BB * 2 * HWP) return;
    int b = idx / (2 * HWP);
    int r = idx - b * (2 * HWP);
    out[(b * 18 + 8) * HWP + r] = 0.0f;
}

// ============================================================================
// Kernel 3: 3x3 conv 64->24 + bias.
// Block = 256 threads = 16 pixel-groups (x4 px) x 4 rows x 4 channel-groups (x6 co).
// Guidance tile staged in smem per ci; weights warp-uniform via __ldg (L1 resident).
// Writes g_oa and the offset part of d_out (channels 0..7 -> 0..7, 8..15 -> 10..17).
// ============================================================================
__global__ void conv_kernel(const float* __restrict__ gin, const float* __restrict__ wgt,
                            const float* __restrict__ bias, float* __restrict__ out) {
    __shared__ float sG[6][72];

    int tid = threadIdx.x;
    int pxg = tid & 15;
    int ry  = (tid >> 4) & 3;
    int chg = tid >> 6;
    int bx = blockIdx.x, by = blockIdx.y, b = blockIdx.z;
    int x0 = bx * 64 + pxg * 4;
    int yy = by * 4 + ry;
    int co0 = chg * 6;

    int gy0 = by * 4 - 1;
    int gx0 = bx * 64 - 1;

    float acc[6][4];
    #pragma unroll
    for (int cc = 0; cc < 6; cc++)
        #pragma unroll
        for (int p = 0; p < 4; p++) acc[cc][p] = 0.0f;

    for (int ci = 0; ci < CIN; ci++) {
        __syncthreads();
        const float* gplane = gin + (b * CIN + ci) * HWP;
        #pragma unroll
        for (int it = 0; it < 2; it++) {
            int idx = tid + it * 256;
            if (idx < 6 * 72) {
                int r = idx / 72, c = idx - r * 72;
                float v = 0.0f;
                if (c < 66) {
                    int gy = gy0 + r, gx = gx0 + c;
                    if (gy >= 0 && gy < HH && gx >= 0 && gx < WW)
                        v = __ldg(gplane + gy * WW + gx);
                }
                sG[r][c] = v;
            }
        }
        __syncthreads();

        float gr[3][6];
        #pragma unroll
        for (int rr = 0; rr < 3; rr++)
            #pragma unroll
            for (int cc2 = 0; cc2 < 6; cc2++)
                gr[rr][cc2] = sG[ry + rr][pxg * 4 + cc2];

        #pragma unroll
        for (int cc = 0; cc < 6; cc++) {
            const float* wp = wgt + ((co0 + cc) * CIN + ci) * 9;
            float wr[9];
            #pragma unroll
            for (int r = 0; r < 9; r++) wr[r] = __ldg(wp + r);
            #pragma unroll
            for (int ky = 0; ky < 3; ky++)
                #pragma unroll
                for (int kx = 0; kx < 3; kx++)
                    #pragma unroll
                    for (int p = 0; p < 4; p++)
                        acc[cc][p] = fmaf(gr[ky][p + kx], wr[ky * 3 + kx], acc[cc][p]);
        }
    }

    #pragma unroll
    for (int cc = 0; cc < 6; cc++) {
        int co = co0 + cc;
        float bv = __ldg(bias + co);
        float* oa = g_oa + (b * COUT + co) * HWP + yy * WW + x0;
        float* ofull = nullptr;
        if (co < 16) {
            int oc = (co < 8) ? co : co + 2;
            ofull = out + (b * 18 + oc) * HWP + yy * WW + x0;
        }
        #pragma unroll
        for (int p = 0; p < 4; p++) {
            float v = acc[cc][p] + bv;
            oa[p] = v;
            if (ofull) ofull[p] = v;
        }
    }
}

// ============================================================================
// Kernel 4: fused cos-affinity + confidence + TGASS + softmax.
//
// Scrambled-reshape closed form: for output pixel P and term m, let X = 8P+m.
// Then the sampled channel is c = X / HW, the donor pixel is P2 = X % HW, and
// cos_w[k,P] = sum_m fea[m,P] * bilin(fea[c], coords(P2, k)).
// One thread per X -> P2 is lane-consecutive (coalesced offset reads, local
// feature gathers). 8-lane shfl transpose-reduce leaves lane m with cos_w[k=m];
// epilogue (conf sample, tanh, normalize, 9-way softmax) done in-warp.
// ============================================================================
__global__ void fused_kernel(const float* __restrict__ gtconf,
                             const float* __restrict__ ascp,
                             float* __restrict__ out) {
    int Xg = blockIdx.x * 256 + threadIdx.x;
    int b = Xg / (8 * HWP);
    int X = Xg - b * (8 * HWP);
    int c = X / HWP;
    int P2 = X - c * HWP;
    int P = X >> 3;
    int m = X & 7;
    int i2 = P2 / WW, j2 = P2 - i2 * WW;

    const float* oa_b = g_oa + b * COUT * HWP;
    const float* feac = g_fea + (b * 8 + c) * HWP;
    float fv = g_feahwc[(b * HWP + P) * 8 + m];

    float v[8];
    #pragma unroll
    for (int k = 0; k < 8; k++) {
        float ox = oa_b[(2 * k) * HWP + P2];       // offset[.,k,0]
        float oy = oa_b[(2 * k + 1) * HWP + P2];   // offset[.,k,1]
        float base = (k < 4) ? (float)i2 : (float)j2;  // faithful to ref's repeat bug
        v[k] = fv * bilin0(feac, ox + base, oy + base, HH, WW);
    }

    // ---- 8-lane transpose reduce: lane m ends with sum_m' v_m'[k=m] ----
    int l = threadIdx.x & 31;
    #pragma unroll
    for (int d = 4; d >= 1; d >>= 1) {
        #pragma unroll
        for (int k = 0; k < 8; k++) {
            float o = __shfl_xor_sync(0xffffffffu, v[k], d);
            if (((k ^ l) & d) == 0) v[k] += o;
        }
    }
    float cw = v[m];

    // ---- epilogue: this lane owns k = m for pixel P ----
    int i = P / WW, j = P - i * WW;
    float araw = oa_b[(16 + m) * HWP + P];
    float dy = oa_b[(2 * m) * HWP + P];      // channel 0 = dy
    float dx = oa_b[(2 * m + 1) * HWP + P];  // channel 1 = dx
    const float* gc = gtconf + b * HWP;
    float conf = bilin0(gc, dx + (float)j, dy + (float)i, HH, WW);

    float asc = __ldg(ascp);
    float aff = tanhf(araw * cw) / (asc + 1e-8f);
    aff = aff * conf;

    float s = fabsf(aff);
    s += __shfl_xor_sync(0xffffffffu, s, 1);
    s += __shfl_xor_sync(0xffffffffu, s, 2);
    s += __shfl_xor_sync(0xffffffffu, s, 4);
    float denom = fmaxf(s + 1e-4f, 1.0f);
    float an = aff / denom;

    float t = an;
    t += __shfl_xor_sync(0xffffffffu, t, 1);
    t += __shfl_xor_sync(0xffffffffu, t, 2);
    t += __shfl_xor_sync(0xffffffffu, t, 4);
    float ref = 1.0f - t;

    float mx = an;
    mx = fmaxf(mx, __shfl_xor_sync(0xffffffffu, mx, 1));
    mx = fmaxf(mx, __shfl_xor_sync(0xffffffffu, mx, 2));
    mx = fmaxf(mx, __shfl_xor_sync(0xffffffffu, mx, 4));
    mx = fmaxf(mx, ref);

    float e  = expf(an - mx);
    float er = expf(ref - mx);
    float se = e;
    se += __shfl_xor_sync(0xffffffffu, se, 1);
    se += __shfl_xor_sync(0xffffffffu, se, 2);
    se += __shfl_xor_sync(0xffffffffu, se, 4);
    se += er;
    float inv = 1.0f / se;

    float* outa = out + (size_t)BB * 18 * HWP + (size_t)b * 9 * HWP;
    int oc = (m < 4) ? m : m + 1;
    outa[oc * HWP + P] = e * inv;
    if (m == 0) outa[4 * HWP + P] = er * inv;
}

// ============================================================================
extern "C" void kernel_launch(void* const* d_in, const int* in_sizes, int n_in,
                              void* d_out, int out_size) {
    const float* guidance = (const float*)d_in[0];
    const float* gtconf   = (const float*)d_in[1];
    const float* tgt      = (const float*)d_in[2];
    const float* convw    = (const float*)d_in[3];
    const float* convb    = (const float*)d_in[4];
    const float* asc      = (const float*)d_in[5];
    float* out = (float*)d_out;

    upsample_kernel<<<(BB * HWP + 255) / 256, 256>>>(tgt);
    zero_kernel<<<(BB * 2 * HWP + 255) / 256, 256>>>(out);
    conv_kernel<<<dim3(WW / 64, HH / 4, BB), 256>>>(guidance, convw, convb, out);
    fused_kernel<<<(BB * 8 * HWP) / 256, 256>>>(gtconf, asc, out);
}